// round 5
// baseline (speedup 1.0000x reference)
#include <cuda_runtime.h>
#include <cuda_bf16.h>

// ---------------------------------------------------------------------------
// NGNN GCNConv: h = GCNConv(x) ; relu ; relu(h@Wfc^T+bfc) ; @Wfc2^T+bfc2
// N=100000 nodes, C=128 channels, E=3.2M edges.
// Round 4: ew==1 fast path (half the deg atomics), TILE_R=128 GEMM,
// fused prep kernels, gemm1 placed 4th so ncu profiles it.
// ---------------------------------------------------------------------------

#define MAX_N 100000
#define MAX_E 3200000
#define C 128

__device__ __align__(256) float g_degw  [MAX_N];
__device__ __align__(256) float g_dinv  [MAX_N];
__device__ __align__(256) int   g_cnt   [MAX_N];
__device__ __align__(256) int   g_start [MAX_N];
__device__ __align__(256) int   g_cursor[MAX_N];
__device__ __align__(256) int   g_bsum  [512];
__device__ __align__(256) int   g_boff  [512];
__device__ __align__(256) int2  g_ebuf  [MAX_E];            // {src, norm}
__device__ __align__(256) float g_h     [(size_t)MAX_N * C];
__device__ __align__(256) float g_agg   [(size_t)MAX_N * C];
__device__ __align__(256) float g_h2    [(size_t)MAX_N * C];
__device__ __align__(256) float g_WT    [3][128 * 128];     // transposed weights
__device__ int g_is64;
__device__ int g_not1;   // 1 if any edge_weight != 1.0f

__device__ __forceinline__ long long eidx(const void* ei, long long i) {
    return g_is64 ? ((const long long*)ei)[i]
                  : (long long)((const int*)ei)[i];
}

// ---------------------------------------------------------------------------
// Launch 1: zero per-call scratch; block 0 additionally detects edge_index
// dtype (int64 indices < 2^31 have all-zero odd 32-bit words) + zeros g_not1.
// ---------------------------------------------------------------------------
__global__ void k_pre0(const unsigned int* __restrict__ ei32, int n, long long E) {
    int i = blockIdx.x * blockDim.x + threadIdx.x;
    if (i < n) { g_cnt[i] = 0; g_degw[i] = 0.0f; }
    if (blockIdx.x == 0) {
        __shared__ unsigned s_any;
        if (threadIdx.x == 0) { s_any = 0u; g_not1 = 0; }
        __syncthreads();
        long long lim = (E < 4096) ? E : 4096;
        unsigned any = 0u;
        for (long long j = threadIdx.x; j < lim; j += blockDim.x)
            any |= ei32[2 * j + 1];
        if (any) atomicOr(&s_any, 1u);
        __syncthreads();
        if (threadIdx.x == 0) g_is64 = (s_any == 0u) ? 1 : 0;
    }
}

// ---------------------------------------------------------------------------
// Launch 2: blocks [0,192): transpose the 3 weight matrices.
//           blocks [192,704): check edge_weight == 1.0 everywhere.
// ---------------------------------------------------------------------------
__global__ void k_prep(const float* __restrict__ W0,
                       const float* __restrict__ W1,
                       const float* __restrict__ W2,
                       const float* __restrict__ ew, long long E) {
    if (blockIdx.x < 192) {
        int which = blockIdx.x >> 6;
        int idx = ((blockIdx.x & 63) << 8) + threadIdx.x;
        const float* W = (which == 0) ? W0 : (which == 1) ? W1 : W2;
        int k = idx >> 7, j = idx & 127;
        g_WT[which][idx] = W[j * 128 + k];
    } else {
        int bad = 0;
        long long stride = 512LL * 256LL;
        for (long long i = (long long)(blockIdx.x - 192) * 256 + threadIdx.x;
             i < E; i += stride)
            if (ew[i] != 1.0f) bad = 1;
        if (bad) atomicOr(&g_not1, 1);
    }
}

// Launch 3: per-dst edge counts (single atomic per edge)
__global__ void k_cnt(const void* __restrict__ ei, long long E) {
    long long e = (long long)blockIdx.x * blockDim.x + threadIdx.x;
    if (e >= E) return;
    long long d = eidx(ei, E + e);
    atomicAdd(&g_cnt[d], 1);
}

// Launch 5: weighted degree — no-op unless some edge_weight != 1
__global__ void k_degw(const void* __restrict__ ei,
                       const float* __restrict__ ew, long long E) {
    if (!g_not1) return;
    long long e = (long long)blockIdx.x * blockDim.x + threadIdx.x;
    if (e >= E) return;
    long long d = eidx(ei, E + e);
    atomicAdd(&g_degw[d], ew[e]);
}

// ---- exclusive prefix sum over g_cnt (3 stages); dinv fused into stage C ----
__global__ void k_scanA(int n) {
    __shared__ int sm[256];
    int t = threadIdx.x;
    int i = blockIdx.x * 256 + t;
    sm[t] = (i < n) ? g_cnt[i] : 0;
    __syncthreads();
    for (int s = 128; s > 0; s >>= 1) {
        if (t < s) sm[t] += sm[t + s];
        __syncthreads();
    }
    if (t == 0) g_bsum[blockIdx.x] = sm[0];
}

__global__ void k_scanB(int nb) {
    __shared__ int sm[512];
    int t = threadIdx.x;
    int v = (t < nb) ? g_bsum[t] : 0;
    sm[t] = v;
    __syncthreads();
    for (int off = 1; off < 512; off <<= 1) {
        int x = (t >= off) ? sm[t - off] : 0;
        __syncthreads();
        sm[t] += x;
        __syncthreads();
    }
    if (t < nb) g_boff[t] = sm[t] - v;  // exclusive
}

__global__ void k_scanC(int n) {
    __shared__ int sm[256];
    int t = threadIdx.x;
    int i = blockIdx.x * 256 + t;
    int v = (i < n) ? g_cnt[i] : 0;
    sm[t] = v;
    __syncthreads();
    for (int off = 1; off < 256; off <<= 1) {
        int x = (t >= off) ? sm[t - off] : 0;
        __syncthreads();
        sm[t] += x;
        __syncthreads();
    }
    if (i < n) {
        int start = g_boff[blockIdx.x] + sm[t] - v;
        g_start[i] = start;
        g_cursor[i] = start;
        float deg = (g_not1 ? g_degw[i] : (float)v) + 1.0f;  // +1 self-loop
        g_dinv[i] = (deg > 0.0f) ? rsqrtf(deg) : 0.0f;
    }
}

// scatter {src, norm} into dst-ordered buckets
__global__ void k_scatter(const void* __restrict__ ei,
                          const float* __restrict__ ew, long long E) {
    long long e = (long long)blockIdx.x * blockDim.x + threadIdx.x;
    if (e >= E) return;
    long long s = eidx(ei, e);
    long long d = eidx(ei, E + e);
    float nm = g_dinv[s] * g_dinv[d];
    if (g_not1) nm *= ew[e];
    int pos = atomicAdd(&g_cursor[d], 1);
    g_ebuf[pos] = make_int2((int)s, __float_as_int(nm));
}

// ---------------------------------------------------------------------------
// Gather: one warp per dst node, lane = 4 channels (float4). Atomic-free.
// agg[d] = dinv[d]^2 * h[d] + sum_bucket norm * h[src]
// ---------------------------------------------------------------------------
__global__ void k_gather(int n) {
    int w = (int)(((long long)blockIdx.x * blockDim.x + threadIdx.x) >> 5);
    if (w >= n) return;
    int lane = threadIdx.x & 31;
    int beg = g_start[w];
    int num = g_cnt[w];
    float di = g_dinv[w];
    float self = di * di;

    float4 hv = *(const float4*)&g_h[(long long)w * C + lane * 4];
    float4 acc = make_float4(hv.x * self, hv.y * self, hv.z * self, hv.w * self);

    int i = 0;
    for (; i + 4 <= num; i += 4) {
        int2 e0 = g_ebuf[beg + i];
        int2 e1 = g_ebuf[beg + i + 1];
        int2 e2 = g_ebuf[beg + i + 2];
        int2 e3 = g_ebuf[beg + i + 3];
        float4 h0 = *(const float4*)&g_h[(long long)e0.x * C + lane * 4];
        float4 h1 = *(const float4*)&g_h[(long long)e1.x * C + lane * 4];
        float4 h2 = *(const float4*)&g_h[(long long)e2.x * C + lane * 4];
        float4 h3 = *(const float4*)&g_h[(long long)e3.x * C + lane * 4];
        float n0 = __int_as_float(e0.y), n1 = __int_as_float(e1.y);
        float n2 = __int_as_float(e2.y), n3 = __int_as_float(e3.y);
        acc.x += n0 * h0.x; acc.y += n0 * h0.y; acc.z += n0 * h0.z; acc.w += n0 * h0.w;
        acc.x += n1 * h1.x; acc.y += n1 * h1.y; acc.z += n1 * h1.z; acc.w += n1 * h1.w;
        acc.x += n2 * h2.x; acc.y += n2 * h2.y; acc.z += n2 * h2.z; acc.w += n2 * h2.w;
        acc.x += n3 * h3.x; acc.y += n3 * h3.y; acc.z += n3 * h3.z; acc.w += n3 * h3.w;
    }
    for (; i < num; i++) {
        int2 e0 = g_ebuf[beg + i];
        float4 h0 = *(const float4*)&g_h[(long long)e0.x * C + lane * 4];
        float n0 = __int_as_float(e0.y);
        acc.x += n0 * h0.x; acc.y += n0 * h0.y; acc.z += n0 * h0.z; acc.w += n0 * h0.w;
    }
    *(float4*)&g_agg[(long long)w * C + lane * 4] = acc;
}

// ---------------------------------------------------------------------------
// 128-wide GEMM with f32x2 packed FMA (2x fp32 throughput, exact fp32).
// Cout[i,j] = post( sum_k pre(A[i,k]) * W[j,k] ),  WT pre-transposed.
// Block 512 thr, tile 128 rows x 128 cols, 4 rows x 8 cols per thread.
// ---------------------------------------------------------------------------
#define WS_STRIDE 132
#define TILE_R 128
#define GEMM_SMEM_BYTES ((128 * WS_STRIDE + TILE_R * 128) * 4)

template <int PRE, int POSTB, int POSTR>
__global__ __launch_bounds__(512, 1) void k_gemm128(
    const float* __restrict__ A, const float* __restrict__ WT,
    const float* __restrict__ preb, const float* __restrict__ postb,
    float* __restrict__ Cout, int n) {
    extern __shared__ float smem[];
    float* Ws = smem;                       // [128][132]  Ws[k][j]
    float* As = smem + 128 * WS_STRIDE;     // [128][128]

    int tid = threadIdx.x;
    for (int idx = tid; idx < 128 * 128; idx += 512)
        Ws[(idx >> 7) * WS_STRIDE + (idx & 127)] = WT[idx];  // conflict-free

    int row0 = blockIdx.x * TILE_R;
    for (int idx = tid; idx < TILE_R * 128; idx += 512) {
        int r = idx >> 7, k = idx & 127;
        int row = row0 + r;
        float v = 0.0f;
        if (row < n) {
            v = A[(long long)row * C + k];
            if (PRE) v = fmaxf(v + preb[k], 0.0f);
        }
        As[idx] = v;
    }
    __syncthreads();

    int cg = tid & 15, rg = tid >> 4;       // rg: 0..31
    int cbase = cg * 8, rbase = rg * 4;

    unsigned long long acc[4][4];
#pragma unroll
    for (int r = 0; r < 4; r++)
#pragma unroll
        for (int p = 0; p < 4; p++) acc[r][p] = 0ull;

#pragma unroll 4
    for (int k = 0; k < 128; k++) {
        ulonglong2 wa = *(const ulonglong2*)&Ws[k * WS_STRIDE + cbase];
        ulonglong2 wb = *(const ulonglong2*)&Ws[k * WS_STRIDE + cbase + 4];
#pragma unroll
        for (int r = 0; r < 4; r++) {
            float a = As[(rbase + r) * 128 + k];
            unsigned long long aa;
            asm("mov.b64 %0, {%1, %1};" : "=l"(aa) : "f"(a));
            asm("fma.rn.f32x2 %0, %1, %2, %0;" : "+l"(acc[r][0]) : "l"(aa), "l"(wa.x));
            asm("fma.rn.f32x2 %0, %1, %2, %0;" : "+l"(acc[r][1]) : "l"(aa), "l"(wa.y));
            asm("fma.rn.f32x2 %0, %1, %2, %0;" : "+l"(acc[r][2]) : "l"(aa), "l"(wb.x));
            asm("fma.rn.f32x2 %0, %1, %2, %0;" : "+l"(acc[r][3]) : "l"(aa), "l"(wb.y));
        }
    }

#pragma unroll
    for (int r = 0; r < 4; r++) {
        int row = row0 + rbase + r;
        if (row >= n) continue;
        float o[8];
#pragma unroll
        for (int p = 0; p < 4; p++)
            asm("mov.b64 {%0, %1}, %2;"
                : "=f"(o[2 * p]), "=f"(o[2 * p + 1]) : "l"(acc[r][p]));
        if (POSTB) {
#pragma unroll
            for (int j = 0; j < 8; j++) o[j] += postb[cbase + j];
        }
        if (POSTR) {
#pragma unroll
            for (int j = 0; j < 8; j++) o[j] = fmaxf(o[j], 0.0f);
        }
        *(float4*)&Cout[(long long)row * C + cbase] =
            make_float4(o[0], o[1], o[2], o[3]);
        *(float4*)&Cout[(long long)row * C + cbase + 4] =
            make_float4(o[4], o[5], o[6], o[7]);
    }
}

// ---------------------------------------------------------------------------
extern "C" void kernel_launch(void* const* d_in, const int* in_sizes, int n_in,
                              void* d_out, int out_size) {
    const float* x  = (const float*)d_in[0];
    const void*  ei = d_in[1];
    const float* ew = (const float*)d_in[2];
    const float* Wc = (const float*)d_in[3];
    const float* bc = (const float*)d_in[4];
    const float* Wf = (const float*)d_in[5];
    const float* bf = (const float*)d_in[6];
    const float* W2 = (const float*)d_in[7];
    const float* b2 = (const float*)d_in[8];
    float* out = (float*)d_out;

    int n = in_sizes[0] / C;
    long long E = in_sizes[2];
    int nb = (n + 255) / 256;
    int gemm_blocks = (n + TILE_R - 1) / TILE_R;
    unsigned eblocks = (unsigned)((E + 255) / 256);

    cudaFuncSetAttribute(k_gemm128<0, 0, 0>,
                         cudaFuncAttributeMaxDynamicSharedMemorySize, GEMM_SMEM_BYTES);
    cudaFuncSetAttribute(k_gemm128<1, 1, 1>,
                         cudaFuncAttributeMaxDynamicSharedMemorySize, GEMM_SMEM_BYTES);
    cudaFuncSetAttribute(k_gemm128<0, 1, 0>,
                         cudaFuncAttributeMaxDynamicSharedMemorySize, GEMM_SMEM_BYTES);

    float* g_h_p;   cudaGetSymbolAddress((void**)&g_h_p,   g_h);
    float* g_agg_p; cudaGetSymbolAddress((void**)&g_agg_p, g_agg);
    float* g_h2_p;  cudaGetSymbolAddress((void**)&g_h2_p,  g_h2);
    float* g_WT_p;  cudaGetSymbolAddress((void**)&g_WT_p,  g_WT);
    const float* WTc = g_WT_p;
    const float* WTf = g_WT_p + 16384;
    const float* WT2 = g_WT_p + 32768;

    // 1. zero scratch + dtype detect
    k_pre0<<<nb, 256>>>((const unsigned int*)ei, n, E);
    // 2. weight transpose + edge_weight==1 check
    k_prep<<<192 + 512, 256>>>(Wc, Wf, W2, ew, E);
    // 3. per-dst counts
    k_cnt<<<eblocks, 256>>>(ei, E);
    // 4. h = x @ Wc^T        <-- 4th launch: ncu profiles this one
    k_gemm128<0, 0, 0><<<gemm_blocks, 512, GEMM_SMEM_BYTES>>>(
        x, WTc, nullptr, nullptr, g_h_p, n);
    // 5. weighted degree (no-op when all weights are 1)
    k_degw<<<eblocks, 256>>>(ei, ew, E);
    // 6-8. exclusive prefix sum of counts (+dinv fused in C)
    k_scanA<<<nb, 256>>>(n);
    k_scanB<<<1, 512>>>(nb);
    k_scanC<<<nb, 256>>>(n);
    // 9. scatter edges into dst buckets
    k_scatter<<<eblocks, 256>>>(ei, ew, E);
    // 10. atomic-free gather (includes self-loop term)
    k_gather<<<(n * 32 + 255) / 256, 256>>>(n);
    // 11. h2 = relu( relu(agg + bc) @ Wf^T + bf )
    k_gemm128<1, 1, 1><<<gemm_blocks, 512, GEMM_SMEM_BYTES>>>(
        g_agg_p, WTf, bc, bf, g_h2_p, n);
    // 12. out = h2 @ W2^T + b2
    k_gemm128<0, 1, 0><<<gemm_blocks, 512, GEMM_SMEM_BYTES>>>(
        g_h2_p, WT2, nullptr, b2, out, n);
}

// round 7
// speedup vs baseline: 1.2279x; 1.2279x over previous
#include <cuda_runtime.h>
#include <cuda_bf16.h>

// ---------------------------------------------------------------------------
// NGNN GCNConv: h = GCNConv(x) ; relu ; relu(h@Wfc^T+bfc) ; @Wfc2^T+bfc2
// N=100000 nodes, C=128 channels, E=3.2M edges.
// Round 6: crossbar-balanced GEMM (8x8 thread tiles, duplicated-A smem for
// mov-free f32x2 pairs, K-chunked smem, 2 CTAs/SM).
// ---------------------------------------------------------------------------

#define MAX_N 100000
#define MAX_E 3200000
#define C 128

__device__ __align__(256) float g_degw  [MAX_N];
__device__ __align__(256) float g_dinv  [MAX_N];
__device__ __align__(256) int   g_cnt   [MAX_N];
__device__ __align__(256) int   g_start [MAX_N];
__device__ __align__(256) int   g_cursor[MAX_N];
__device__ __align__(256) int   g_bsum  [512];
__device__ __align__(256) int   g_boff  [512];
__device__ __align__(256) int2  g_ebuf  [MAX_E];            // {src, norm}
__device__ __align__(256) float g_h     [(size_t)MAX_N * C];
__device__ __align__(256) float g_agg   [(size_t)MAX_N * C];
__device__ __align__(256) float g_h2    [(size_t)MAX_N * C];
__device__ __align__(256) float g_WT    [3][128 * 128];     // transposed weights
__device__ int g_is64;
__device__ int g_not1;   // 1 if any edge_weight != 1.0f

__device__ __forceinline__ long long eidx(const void* ei, long long i) {
    return g_is64 ? ((const long long*)ei)[i]
                  : (long long)((const int*)ei)[i];
}

// ---------------------------------------------------------------------------
// Launch 1: zero scratch; block 0 detects edge_index dtype + clears g_not1.
// ---------------------------------------------------------------------------
__global__ void k_pre0(const unsigned int* __restrict__ ei32, int n, long long E) {
    int i = blockIdx.x * blockDim.x + threadIdx.x;
    if (i < n) { g_cnt[i] = 0; g_degw[i] = 0.0f; }
    if (blockIdx.x == 0) {
        __shared__ unsigned s_any;
        if (threadIdx.x == 0) { s_any = 0u; g_not1 = 0; }
        __syncthreads();
        long long lim = (E < 4096) ? E : 4096;
        unsigned any = 0u;
        for (long long j = threadIdx.x; j < lim; j += blockDim.x)
            any |= ei32[2 * j + 1];
        if (any) atomicOr(&s_any, 1u);
        __syncthreads();
        if (threadIdx.x == 0) g_is64 = (s_any == 0u) ? 1 : 0;
    }
}

// ---------------------------------------------------------------------------
// Launch 2: blocks [0,192): transpose weights; [192,704): ew==1.0 check.
// ---------------------------------------------------------------------------
__global__ void k_prep(const float* __restrict__ W0,
                       const float* __restrict__ W1,
                       const float* __restrict__ W2,
                       const float* __restrict__ ew, long long E) {
    if (blockIdx.x < 192) {
        int which = blockIdx.x >> 6;
        int idx = ((blockIdx.x & 63) << 8) + threadIdx.x;
        const float* W = (which == 0) ? W0 : (which == 1) ? W1 : W2;
        int k = idx >> 7, j = idx & 127;
        g_WT[which][idx] = W[j * 128 + k];
    } else {
        int bad = 0;
        long long stride = 512LL * 256LL;
        for (long long i = (long long)(blockIdx.x - 192) * 256 + threadIdx.x;
             i < E; i += stride)
            if (ew[i] != 1.0f) bad = 1;
        if (bad) atomicOr(&g_not1, 1);
    }
}

// Launch 3: per-dst edge counts (single atomic per edge)
__global__ void k_cnt(const void* __restrict__ ei, long long E) {
    long long e = (long long)blockIdx.x * blockDim.x + threadIdx.x;
    if (e >= E) return;
    long long d = eidx(ei, E + e);
    atomicAdd(&g_cnt[d], 1);
}

// weighted degree — no-op unless some edge_weight != 1
__global__ void k_degw(const void* __restrict__ ei,
                       const float* __restrict__ ew, long long E) {
    if (!g_not1) return;
    long long e = (long long)blockIdx.x * blockDim.x + threadIdx.x;
    if (e >= E) return;
    long long d = eidx(ei, E + e);
    atomicAdd(&g_degw[d], ew[e]);
}

// ---- exclusive prefix sum over g_cnt (3 stages); dinv fused into stage C ----
__global__ void k_scanA(int n) {
    __shared__ int sm[256];
    int t = threadIdx.x;
    int i = blockIdx.x * 256 + t;
    sm[t] = (i < n) ? g_cnt[i] : 0;
    __syncthreads();
    for (int s = 128; s > 0; s >>= 1) {
        if (t < s) sm[t] += sm[t + s];
        __syncthreads();
    }
    if (t == 0) g_bsum[blockIdx.x] = sm[0];
}

__global__ void k_scanB(int nb) {
    __shared__ int sm[512];
    int t = threadIdx.x;
    int v = (t < nb) ? g_bsum[t] : 0;
    sm[t] = v;
    __syncthreads();
    for (int off = 1; off < 512; off <<= 1) {
        int x = (t >= off) ? sm[t - off] : 0;
        __syncthreads();
        sm[t] += x;
        __syncthreads();
    }
    if (t < nb) g_boff[t] = sm[t] - v;  // exclusive
}

__global__ void k_scanC(int n) {
    __shared__ int sm[256];
    int t = threadIdx.x;
    int i = blockIdx.x * 256 + t;
    int v = (i < n) ? g_cnt[i] : 0;
    sm[t] = v;
    __syncthreads();
    for (int off = 1; off < 256; off <<= 1) {
        int x = (t >= off) ? sm[t - off] : 0;
        __syncthreads();
        sm[t] += x;
        __syncthreads();
    }
    if (i < n) {
        int start = g_boff[blockIdx.x] + sm[t] - v;
        g_start[i] = start;
        g_cursor[i] = start;
        float deg = (g_not1 ? g_degw[i] : (float)v) + 1.0f;  // +1 self-loop
        g_dinv[i] = (deg > 0.0f) ? rsqrtf(deg) : 0.0f;
    }
}

// scatter {src, norm} into dst-ordered buckets
__global__ void k_scatter(const void* __restrict__ ei,
                          const float* __restrict__ ew, long long E) {
    long long e = (long long)blockIdx.x * blockDim.x + threadIdx.x;
    if (e >= E) return;
    long long s = eidx(ei, e);
    long long d = eidx(ei, E + e);
    float nm = g_dinv[s] * g_dinv[d];
    if (g_not1) nm *= ew[e];
    int pos = atomicAdd(&g_cursor[d], 1);
    g_ebuf[pos] = make_int2((int)s, __float_as_int(nm));
}

// ---------------------------------------------------------------------------
// Gather: one warp per dst node, lane = 4 channels (float4). Atomic-free.
// ---------------------------------------------------------------------------
__global__ void k_gather(int n) {
    int w = (int)(((long long)blockIdx.x * blockDim.x + threadIdx.x) >> 5);
    if (w >= n) return;
    int lane = threadIdx.x & 31;
    int beg = g_start[w];
    int num = g_cnt[w];
    float di = g_dinv[w];
    float self = di * di;

    float4 hv = *(const float4*)&g_h[(long long)w * C + lane * 4];
    float4 acc = make_float4(hv.x * self, hv.y * self, hv.z * self, hv.w * self);

    int i = 0;
    for (; i + 4 <= num; i += 4) {
        int2 e0 = g_ebuf[beg + i];
        int2 e1 = g_ebuf[beg + i + 1];
        int2 e2 = g_ebuf[beg + i + 2];
        int2 e3 = g_ebuf[beg + i + 3];
        float4 h0 = *(const float4*)&g_h[(long long)e0.x * C + lane * 4];
        float4 h1 = *(const float4*)&g_h[(long long)e1.x * C + lane * 4];
        float4 h2 = *(const float4*)&g_h[(long long)e2.x * C + lane * 4];
        float4 h3 = *(const float4*)&g_h[(long long)e3.x * C + lane * 4];
        float n0 = __int_as_float(e0.y), n1 = __int_as_float(e1.y);
        float n2 = __int_as_float(e2.y), n3 = __int_as_float(e3.y);
        acc.x += n0 * h0.x; acc.y += n0 * h0.y; acc.z += n0 * h0.z; acc.w += n0 * h0.w;
        acc.x += n1 * h1.x; acc.y += n1 * h1.y; acc.z += n1 * h1.z; acc.w += n1 * h1.w;
        acc.x += n2 * h2.x; acc.y += n2 * h2.y; acc.z += n2 * h2.z; acc.w += n2 * h2.w;
        acc.x += n3 * h3.x; acc.y += n3 * h3.y; acc.z += n3 * h3.z; acc.w += n3 * h3.w;
    }
    for (; i < num; i++) {
        int2 e0 = g_ebuf[beg + i];
        float4 h0 = *(const float4*)&g_h[(long long)e0.x * C + lane * 4];
        float n0 = __int_as_float(e0.y);
        acc.x += n0 * h0.x; acc.y += n0 * h0.y; acc.z += n0 * h0.z; acc.w += n0 * h0.w;
    }
    *(float4*)&g_agg[(long long)w * C + lane * 4] = acc;
}

// ---------------------------------------------------------------------------
// GEMM: 128x128 CTA tile, 256 threads, 8x8 per thread, f32x2 FMA.
// A stored DUPLICATED in smem (As[r][2k]=As[r][2k+1]=a) -> LDS.64 yields the
// {a,a} pair directly (broadcast, 1 phase, no movs). W pairs natural from
// LDS.128. K chunked by 32 -> 53.8KB smem -> 2 CTAs/SM.
// ---------------------------------------------------------------------------
#define KC 32
#define AD_STRIDE 72      // 2*KC + 8 pad (floats); row start 288B, 16B aligned
#define WS_STRIDE 132
#define GEMM_SMEM_BYTES ((128 * AD_STRIDE + KC * WS_STRIDE) * 4)

template <int PRE, int POSTB, int POSTR>
__global__ __launch_bounds__(256, 2) void k_gemm128(
    const float* __restrict__ A, const float* __restrict__ WT,
    const float* __restrict__ preb, const float* __restrict__ postb,
    float* __restrict__ Cout, int n) {
    extern __shared__ float smem[];
    float* As = smem;                    // [128][AD_STRIDE]  dup pairs
    float* Ws = smem + 128 * AD_STRIDE;  // [KC][WS_STRIDE]

    int tid = threadIdx.x;
    int row0 = blockIdx.x * 128;
    int cg = tid & 15, rg = tid >> 4;
    int cbase = cg * 8, rbase = rg * 8;

    unsigned long long acc[8][4];
#pragma unroll
    for (int j = 0; j < 8; j++)
#pragma unroll
        for (int p = 0; p < 4; p++) acc[j][p] = 0ull;

    for (int kc = 0; kc < 128; kc += KC) {
        // Ws[k][j] = WT[(kc+k)*128 + j]  (coalesced)
        for (int idx = tid; idx < KC * 128; idx += 256) {
            int kk = idx >> 7, j = idx & 127;
            Ws[kk * WS_STRIDE + j] = WT[(kc + kk) * 128 + j];
        }
        // As dup fill: 128 rows x KC/4 float4
        for (int idx = tid; idx < 128 * (KC / 4); idx += 256) {
            int r = idx >> 3, q = idx & 7;       // KC/4 = 8
            int row = row0 + r;
            float4 v = make_float4(0.f, 0.f, 0.f, 0.f);
            if (row < n) {
                v = *(const float4*)&A[(long long)row * C + kc + 4 * q];
                if (PRE) {
                    v.x = fmaxf(v.x + preb[kc + 4 * q + 0], 0.0f);
                    v.y = fmaxf(v.y + preb[kc + 4 * q + 1], 0.0f);
                    v.z = fmaxf(v.z + preb[kc + 4 * q + 2], 0.0f);
                    v.w = fmaxf(v.w + preb[kc + 4 * q + 3], 0.0f);
                }
            }
            float* p = &As[r * AD_STRIDE + 8 * q];
            *(float4*)&p[0] = make_float4(v.x, v.x, v.y, v.y);
            *(float4*)&p[4] = make_float4(v.z, v.z, v.w, v.w);
        }
        __syncthreads();

#pragma unroll 4
        for (int k = 0; k < KC; k++) {
            ulonglong2 wa = *(const ulonglong2*)&Ws[k * WS_STRIDE + cbase];
            ulonglong2 wb = *(const ulonglong2*)&Ws[k * WS_STRIDE + cbase + 4];
#pragma unroll
            for (int j = 0; j < 8; j++) {
                unsigned long long ap =
                    *(const unsigned long long*)&As[(rbase + j) * AD_STRIDE + 2 * k];
                asm("fma.rn.f32x2 %0, %1, %2, %0;" : "+l"(acc[j][0]) : "l"(ap), "l"(wa.x));
                asm("fma.rn.f32x2 %0, %1, %2, %0;" : "+l"(acc[j][1]) : "l"(ap), "l"(wa.y));
                asm("fma.rn.f32x2 %0, %1, %2, %0;" : "+l"(acc[j][2]) : "l"(ap), "l"(wb.x));
                asm("fma.rn.f32x2 %0, %1, %2, %0;" : "+l"(acc[j][3]) : "l"(ap), "l"(wb.y));
            }
        }
        __syncthreads();
    }

#pragma unroll
    for (int j = 0; j < 8; j++) {
        int row = row0 + rbase + j;
        if (row >= n) continue;
        float o[8];
#pragma unroll
        for (int p = 0; p < 4; p++)
            asm("mov.b64 {%0, %1}, %2;"
                : "=f"(o[2 * p]), "=f"(o[2 * p + 1]) : "l"(acc[j][p]));
        if (POSTB) {
#pragma unroll
            for (int c = 0; c < 8; c++) o[c] += postb[cbase + c];
        }
        if (POSTR) {
#pragma unroll
            for (int c = 0; c < 8; c++) o[c] = fmaxf(o[c], 0.0f);
        }
        *(float4*)&Cout[(long long)row * C + cbase] =
            make_float4(o[0], o[1], o[2], o[3]);
        *(float4*)&Cout[(long long)row * C + cbase + 4] =
            make_float4(o[4], o[5], o[6], o[7]);
    }
}

// ---------------------------------------------------------------------------
extern "C" void kernel_launch(void* const* d_in, const int* in_sizes, int n_in,
                              void* d_out, int out_size) {
    const float* x  = (const float*)d_in[0];
    const void*  ei = d_in[1];
    const float* ew = (const float*)d_in[2];
    const float* Wc = (const float*)d_in[3];
    const float* bc = (const float*)d_in[4];
    const float* Wf = (const float*)d_in[5];
    const float* bf = (const float*)d_in[6];
    const float* W2 = (const float*)d_in[7];
    const float* b2 = (const float*)d_in[8];
    float* out = (float*)d_out;

    int n = in_sizes[0] / C;
    long long E = in_sizes[2];
    int nb = (n + 255) / 256;
    int gemm_blocks = (n + 127) / 128;
    unsigned eblocks = (unsigned)((E + 255) / 256);

    cudaFuncSetAttribute(k_gemm128<0, 0, 0>,
                         cudaFuncAttributeMaxDynamicSharedMemorySize, GEMM_SMEM_BYTES);
    cudaFuncSetAttribute(k_gemm128<1, 1, 1>,
                         cudaFuncAttributeMaxDynamicSharedMemorySize, GEMM_SMEM_BYTES);
    cudaFuncSetAttribute(k_gemm128<0, 1, 0>,
                         cudaFuncAttributeMaxDynamicSharedMemorySize, GEMM_SMEM_BYTES);

    float* g_h_p;   cudaGetSymbolAddress((void**)&g_h_p,   g_h);
    float* g_agg_p; cudaGetSymbolAddress((void**)&g_agg_p, g_agg);
    float* g_h2_p;  cudaGetSymbolAddress((void**)&g_h2_p,  g_h2);
    float* g_WT_p;  cudaGetSymbolAddress((void**)&g_WT_p,  g_WT);
    const float* WTc = g_WT_p;
    const float* WTf = g_WT_p + 16384;
    const float* WT2 = g_WT_p + 32768;

    // 1. zero scratch + dtype detect
    k_pre0<<<nb, 256>>>((const unsigned int*)ei, n, E);
    // 2. weight transpose + edge_weight==1 check
    k_prep<<<192 + 512, 256>>>(Wc, Wf, W2, ew, E);
    // 3. per-dst counts
    k_cnt<<<eblocks, 256>>>(ei, E);
    // 4. h = x @ Wc^T        <-- 4th launch: ncu profiles this one
    k_gemm128<0, 0, 0><<<gemm_blocks, 256, GEMM_SMEM_BYTES>>>(
        x, WTc, nullptr, nullptr, g_h_p, n);
    // 5. weighted degree (no-op when all weights are 1)
    k_degw<<<eblocks, 256>>>(ei, ew, E);
    // 6-8. exclusive prefix sum of counts (+dinv fused in C)
    k_scanA<<<nb, 256>>>(n);
    k_scanB<<<1, 512>>>(nb);
    k_scanC<<<nb, 256>>>(n);
    // 9. scatter edges into dst buckets
    k_scatter<<<eblocks, 256>>>(ei, ew, E);
    // 10. atomic-free gather (includes self-loop term)
    k_gather<<<(n * 32 + 255) / 256, 256>>>(n);
    // 11. h2 = relu( relu(agg + bc) @ Wf^T + bf )
    k_gemm128<1, 1, 1><<<gemm_blocks, 256, GEMM_SMEM_BYTES>>>(
        g_agg_p, WTf, bc, bf, g_h2_p, n);
    // 12. out = h2 @ W2^T + b2
    k_gemm128<0, 1, 0><<<gemm_blocks, 256, GEMM_SMEM_BYTES>>>(
        g_h2_p, WT2, nullptr, b2, out, n);
}